// round 12
// baseline (speedup 1.0000x reference)
#include <cuda_runtime.h>
#include <cuda_bf16.h>
#include <cuda_fp16.h>
#include <cstdint>

#define BT_TOK 32768      // B*T = 16*2048
#define IN_DIM 768
#define ENC 512
#define CDIM 128
#define NCB 8
#define CBS 1024

// ---------------- scratch (static device globals; no allocations) ----------
__device__ float g_R[BT_TOK * ENC];                    // residual (64MB)
__device__ float g_Ze[BT_TOK * CDIM];                  // z_e fp32 (16MB)
__device__ __nv_bfloat16 g_zeA[(size_t)BT_TOK * CDIM]; // ze bf16 a-plane (8MB)
__device__ __nv_bfloat16 g_cbA[(size_t)NCB * CBS * CDIM]; // cb a-plane (2MB)
__device__ __half g_D[(size_t)BT_TOK * CBS];           // approx distances (64MB)
__device__ float g_cbnorm[NCB * CBS];                  // ||c||^2
__device__ unsigned g_maxC2u[NCB];                     // max ||c||^2 (bits), zero-init
__device__ float g_G[NCB * CBS * ENC];                 // cb @ out_w tables (16MB)
__device__ float g_lossPartial[NCB * BT_TOK];          // deterministic partials

// ---------------- helpers ----------------------------------------------------
__device__ __forceinline__ void cp16(uint32_t smem, const void* gmem) {
    asm volatile("cp.async.cg.shared.global [%0], [%1], 16;\n" :: "r"(smem), "l"(gmem));
}
__device__ __forceinline__ void cp16p(void* smem, const void* gmem) {
    cp16((uint32_t)__cvta_generic_to_shared(smem), gmem);
}
#define CP_COMMIT asm volatile("cp.async.commit_group;\n" ::)
#define CP_WAIT0  asm volatile("cp.async.wait_group 0;\n" ::)
#define CP_WAIT1  asm volatile("cp.async.wait_group 1;\n" ::)

__device__ __forceinline__ unsigned long long pack2(float lo, float hi) {
    unsigned long long r;
    asm("mov.b64 %0, {%1, %2};" : "=l"(r) : "f"(lo), "f"(hi));
    return r;
}
__device__ __forceinline__ void unpack2(float& lo, float& hi, unsigned long long v) {
    asm("mov.b64 {%0, %1}, %2;" : "=f"(lo), "=f"(hi) : "l"(v));
}
__device__ __forceinline__ void fma2(unsigned long long& d, unsigned long long a,
                                     unsigned long long b) {
    asm("fma.rn.f32x2 %0, %1, %2, %0;" : "+l"(d) : "l"(a), "l"(b));
}

__device__ __forceinline__ unsigned fmap(float x) {    // monotonic float->uint
    unsigned ib = __float_as_uint(x);
    return ib ^ ((ib & 0x80000000u) ? 0xffffffffu : 0x80000000u);
}
__device__ __forceinline__ float funmap(unsigned u) {
    unsigned ib = (u & 0x80000000u) ? (u ^ 0x80000000u) : ~u;
    return __uint_as_float(ib);
}

#define LDMX4(r, addr) \
    asm volatile("ldmatrix.sync.aligned.m8n8.x4.shared.b16 {%0,%1,%2,%3}, [%4];" \
                 : "=r"((r)[0]), "=r"((r)[1]), "=r"((r)[2]), "=r"((r)[3]) : "r"(addr))
#define LDMX2(r, addr) \
    asm volatile("ldmatrix.sync.aligned.m8n8.x2.shared.b16 {%0,%1}, [%2];" \
                 : "=r"((r)[0]), "=r"((r)[1]) : "r"(addr))
#define MMA16816(c, a, b) \
    asm volatile("mma.sync.aligned.m16n8k16.row.col.f32.bf16.bf16.f32 " \
                 "{%0,%1,%2,%3}, {%4,%5,%6,%7}, {%8,%9}, {%0,%1,%2,%3};" \
                 : "+f"((c)[0]), "+f"((c)[1]), "+f"((c)[2]), "+f"((c)[3]) \
                 : "r"((a)[0]), "r"((a)[1]), "r"((a)[2]), "r"((a)[3]), \
                   "r"((b)[0]), "r"((b)[1]))

// ---------------- SGEMM: 128x128 tile, BK=16, smem DB, FFMA2 core ----------
// C = A @ B (+bias). SPLIT: also emit bf16 a-plane of C.
// Per-output fp32 accumulation chain: k strictly ascending (bit-identical R1-R11).
template<bool BIAS, bool SPLIT>
__global__ __launch_bounds__(256, 2) void sgemm4(
    const float* __restrict__ A, const float* __restrict__ B,
    float* __restrict__ C, const float* __restrict__ bias,
    __nv_bfloat16* __restrict__ splitOut, int K, int N,
    size_t strA, size_t strB, size_t strC)
{
    __shared__ float As[2][16][128];
    __shared__ float Bs[2][16][128];
    A += (size_t)blockIdx.z * strA;
    B += (size_t)blockIdx.z * strB;
    C += (size_t)blockIdx.z * strC;
    const int tid = threadIdx.x;
    const int tx = tid & 15, ty = tid >> 4;
    const int m0 = blockIdx.x * 128;
    const int n0 = blockIdx.y * 128;

    const int ar = tid & 127;
    const int ah = (tid >> 7) * 8;
    const int br = tid >> 4;
    const int bc = (tid & 15) * 4;

    const float* aptr = A + (size_t)(m0 + ar) * K;
    const float* bptr = B + n0;

    const int T = K >> 4;

    float4 av0 = *(const float4*)(aptr + ah);
    float4 av1 = *(const float4*)(aptr + ah + 4);
    cp16p(&Bs[0][br][bc],      bptr + (size_t)br * N + bc);
    cp16p(&Bs[0][br][bc + 64], bptr + (size_t)br * N + bc + 64);
    As[0][ah + 0][ar] = av0.x; As[0][ah + 1][ar] = av0.y;
    As[0][ah + 2][ar] = av0.z; As[0][ah + 3][ar] = av0.w;
    As[0][ah + 4][ar] = av1.x; As[0][ah + 5][ar] = av1.y;
    As[0][ah + 6][ar] = av1.z; As[0][ah + 7][ar] = av1.w;
    CP_COMMIT;
    CP_WAIT0;
    __syncthreads();

    unsigned long long acc2[8][4];
#pragma unroll
    for (int i = 0; i < 8; ++i)
#pragma unroll
        for (int j = 0; j < 4; ++j) acc2[i][j] = 0ull;

    for (int t = 0; t < T; ++t) {
        const int buf = t & 1;
        const bool pf = (t + 1 < T);
        const int kn = (t + 1) << 4;
        if (pf) {
            av0 = *(const float4*)(aptr + kn + ah);
            av1 = *(const float4*)(aptr + kn + ah + 4);
            cp16p(&Bs[buf ^ 1][br][bc],      bptr + (size_t)(kn + br) * N + bc);
            cp16p(&Bs[buf ^ 1][br][bc + 64], bptr + (size_t)(kn + br) * N + bc + 64);
            CP_COMMIT;
        }
#pragma unroll
        for (int k = 0; k < 16; ++k) {
            float a[8];
            *(float4*)(a)     = *(const float4*)&As[buf][k][ty * 8];
            *(float4*)(a + 4) = *(const float4*)&As[buf][k][ty * 8 + 4];
            float4 b0 = *(const float4*)&Bs[buf][k][tx * 8];
            float4 b1 = *(const float4*)&Bs[buf][k][tx * 8 + 4];
            unsigned long long bb[4];
            bb[0] = pack2(b0.x, b0.y); bb[1] = pack2(b0.z, b0.w);
            bb[2] = pack2(b1.x, b1.y); bb[3] = pack2(b1.z, b1.w);
#pragma unroll
            for (int i = 0; i < 8; ++i) {
                unsigned long long ai = pack2(a[i], a[i]);
#pragma unroll
                for (int j = 0; j < 4; ++j) fma2(acc2[i][j], ai, bb[j]);
            }
        }
        if (pf) {
            As[buf ^ 1][ah + 0][ar] = av0.x; As[buf ^ 1][ah + 1][ar] = av0.y;
            As[buf ^ 1][ah + 2][ar] = av0.z; As[buf ^ 1][ah + 3][ar] = av0.w;
            As[buf ^ 1][ah + 4][ar] = av1.x; As[buf ^ 1][ah + 5][ar] = av1.y;
            As[buf ^ 1][ah + 6][ar] = av1.z; As[buf ^ 1][ah + 7][ar] = av1.w;
            CP_WAIT0;
            __syncthreads();
        }
    }

#pragma unroll
    for (int i = 0; i < 8; ++i) {
        float c[8];
#pragma unroll
        for (int j = 0; j < 4; ++j) unpack2(c[2 * j], c[2 * j + 1], acc2[i][j]);
        int m = m0 + ty * 8 + i;
        float* crow = C + (size_t)m * N + n0 + tx * 8;
        if (BIAS) {
#pragma unroll
            for (int j = 0; j < 8; ++j) crow[j] = c[j] + bias[n0 + tx * 8 + j];
        } else {
#pragma unroll
            for (int j = 0; j < 8; ++j) crow[j] = c[j];
        }
        if (SPLIT) {
            __align__(16) __nv_bfloat16 pa[8];
#pragma unroll
            for (int j = 0; j < 8; ++j) pa[j] = __float2bfloat16(c[j]);
            *(uint4*)(splitOut + (size_t)m * CDIM + n0 + tx * 8) = *(const uint4*)pa;
        }
    }
}

// ---------------- codebook a-plane + norms ----------------------------------
__global__ void split_cb_kernel(const float* __restrict__ cb,
                                __nv_bfloat16* __restrict__ out)
{
    size_t i = (size_t)blockIdx.x * blockDim.x + threadIdx.x;
    if (i >= (size_t)NCB * CBS * CDIM) return;
    out[i] = __float2bfloat16(cb[i]);
}

// norms + per-stage max||c||^2 (atomicMax on positive-float bits: order-free)
__global__ void norm_kernel(const float* __restrict__ cb, float* __restrict__ out,
                            unsigned* __restrict__ maxC2u, int rows)
{
    int w = (blockIdx.x * blockDim.x + threadIdx.x) >> 5;
    int lane = threadIdx.x & 31;
    if (w >= rows) return;
    const float* r = cb + (size_t)w * CDIM;
    float s = 0.f;
#pragma unroll
    for (int q = 0; q < 4; ++q) { float v = r[lane + q * 32]; s += v * v; }
#pragma unroll
    for (int off = 16; off >= 1; off >>= 1) s += __shfl_xor_sync(0xffffffffu, s, off);
    if (lane == 0) {
        out[w] = s;
        atomicMax(&maxC2u[w >> 10], __float_as_uint(s));
    }
}

// ---------------- fused dist + certified argmin + update --------------------
// Per CTA: 128 tokens x 1024 codes.
// Phase 1 (identical math to R11): single bf16-a-plane MMA pass; d~ = ||c||^2
//   - 2*(a.a) stored fp16 to g_D; per-row running min of the SAME fp16-rounded
//   values tracked in registers -> smem atomicMin (order-free min => exact
//   same dmin as R11's scan).
// Phase 2 (identical math to R11): margin threshold; rescore candidates with
//   the exact fp32 chain (acc=fma(ze_k,cb_k,acc), k asc; d=cbn-2*acc); key-min.
//   Then codes + loss + R -= G[idx] inline (update arithmetic identical).
#define PSTR 272                        // smem row stride (256B data + 16 pad)
#define P1_B (128 * PSTR)               // 34816
#define P1_BBUF (64 * PSTR)             // 17408
#define P1_TOT (P1_B + 2 * P1_BBUF)     // 69632 dynamic smem
#define ZSTR 132                        // fp32 Ze cache row stride (floats)

__global__ __launch_bounds__(256) void distFused_kernel(
    const __nv_bfloat16* __restrict__ zeA,   // [BT_TOK][128]
    const __nv_bfloat16* __restrict__ cbA,   // stage base [CBS][128]
    const float* __restrict__ cbn,           // stage base [CBS]
    __half* __restrict__ D,                  // [BT_TOK][CBS] scratch
    const float* __restrict__ Ze,            // fp32 z_e
    const float* __restrict__ cb,            // stage base fp32 codebook
    const float* __restrict__ G,             // stage base dec table [CBS][ENC]
    const unsigned* __restrict__ maxC2u, int stage,
    float* __restrict__ out_codes, float* __restrict__ partial,
    float* __restrict__ R)
{
    extern __shared__ char smem[];
    __shared__ unsigned sdmin[128];
    const uint32_t sb = (uint32_t)__cvta_generic_to_shared(smem);
    const int tid = threadIdx.x;
    const int lane = tid & 31, wid = tid >> 5;
    const int rowband = wid & 3;
    const int colhalf = wid >> 2;
    const int gid = lane >> 2, tig = lane & 3;
    const int m0 = blockIdx.x * 128;

    if (tid < 128) sdmin[tid] = 0xffffffffu;

    // ---- phase 1 loads ----
    {
        const __nv_bfloat16* src = zeA + (size_t)m0 * CDIM;
#pragma unroll
        for (int it = 0; it < 8; ++it) {
            int idx = tid + it * 256;
            int row = idx >> 4, piece = idx & 15;
            cp16(sb + row * PSTR + piece * 16, src + (size_t)row * CDIM + piece * 8);
        }
    }
    CP_COMMIT;
    {
#pragma unroll
        for (int it = 0; it < 4; ++it) {
            int idx = tid + it * 256;
            int row = idx >> 4, piece = idx & 15;
            cp16(sb + P1_B + row * PSTR + piece * 16,
                 cbA + (size_t)row * CDIM + piece * 8);
        }
    }
    CP_COMMIT;

    const uint32_t aBase = sb + (rowband * 32 + (lane & 15)) * PSTR + (lane >> 4) * 16;
    const uint32_t bLaneOff = (colhalf * 32 + (lane & 7)) * PSTR +
                              ((lane >> 3) & 1) * 16;

    float c[2][4][4];
#pragma unroll
    for (int rt = 0; rt < 2; ++rt)
#pragma unroll
        for (int ct = 0; ct < 4; ++ct)
#pragma unroll
            for (int v = 0; v < 4; ++v) c[rt][ct][v] = 0.f;

    float rmin[4] = {3.4e38f, 3.4e38f, 3.4e38f, 3.4e38f};  // rows lr0+{0,8,16,24}

    for (int nc = 0; nc < 16; ++nc) {
        const int buf = nc & 1;
        if (nc + 1 < 16) {
            const __nv_bfloat16* src = cbA + (size_t)(nc + 1) * 64 * CDIM;
            const uint32_t dst = sb + P1_B + (buf ^ 1) * P1_BBUF;
#pragma unroll
            for (int it = 0; it < 4; ++it) {
                int idx = tid + it * 256;
                int row = idx >> 4, piece = idx & 15;
                cp16(dst + row * PSTR + piece * 16,
                     src + (size_t)row * CDIM + piece * 8);
            }
            CP_COMMIT;
            CP_WAIT1;
        } else {
            CP_WAIT0;
        }
        __syncthreads();

        const uint32_t bBase = sb + P1_B + buf * P1_BBUF + bLaneOff;
#pragma unroll
        for (int kc = 0; kc < 2; ++kc) {
#pragma unroll
            for (int ks = 0; ks < 4; ++ks) {
                const uint32_t off = kc * 128 + ks * 32;
                uint32_t a[2][4];
                LDMX4(a[0], aBase + off);
                LDMX4(a[1], aBase + 16 * PSTR + off);
                uint32_t b[4][2];
#pragma unroll
                for (int ct = 0; ct < 4; ++ct)
                    LDMX2(b[ct], bBase + ct * 8 * PSTR + off);
#pragma unroll
                for (int rt = 0; rt < 2; ++rt)
#pragma unroll
                    for (int ct = 0; ct < 4; ++ct)
                        MMA16816(c[rt][ct], a[rt], b[ct]);
            }
        }

        // write fp16 approx distances + track per-row running min (fp16-rounded)
        {
            const int colb = nc * 64 + colhalf * 32;
#pragma unroll
            for (int rt = 0; rt < 2; ++rt) {
                const int row = m0 + rowband * 32 + rt * 16 + gid;
                __half2* d0 = (__half2*)(D + (size_t)row * CBS);
                __half2* d1 = (__half2*)(D + (size_t)(row + 8) * CBS);
#pragma unroll
                for (int ct = 0; ct < 4; ++ct) {
                    const int col = colb + ct * 8 + tig * 2;
                    const float cn0 = cbn[col], cn1 = cbn[col + 1];
                    __half2 h0 = __floats2half2_rn(cn0 - 2.0f * c[rt][ct][0],
                                                   cn1 - 2.0f * c[rt][ct][1]);
                    __half2 h1 = __floats2half2_rn(cn0 - 2.0f * c[rt][ct][2],
                                                   cn1 - 2.0f * c[rt][ct][3]);
                    d0[col >> 1] = h0;
                    d1[col >> 1] = h1;
                    float2 f0 = __half22float2(h0);
                    float2 f1 = __half22float2(h1);
                    rmin[rt * 2]     = fminf(rmin[rt * 2],     fminf(f0.x, f0.y));
                    rmin[rt * 2 + 1] = fminf(rmin[rt * 2 + 1], fminf(f1.x, f1.y));
                    c[rt][ct][0] = 0.f; c[rt][ct][1] = 0.f;
                    c[rt][ct][2] = 0.f; c[rt][ct][3] = 0.f;
                }
            }
        }
        __syncthreads();
    }

    // publish per-row minima (order-free)
#pragma unroll
    for (int rt = 0; rt < 2; ++rt) {
        const int lr = rowband * 32 + rt * 16 + gid;
        atomicMin(&sdmin[lr],     fmap(rmin[rt * 2]));
        atomicMin(&sdmin[lr + 8], fmap(rmin[rt * 2 + 1]));
    }
    __syncthreads();

    // ---- phase 2: load fp32 Ze into (re-purposed) smem ----
    float* zs = (float*)smem;
    {
        const float* src = Ze + (size_t)m0 * CDIM;
#pragma unroll
        for (int it = 0; it < 16; ++it) {
            int idx = tid + it * 256;        // 0..4095 float4 units
            int row = idx >> 5, q = idx & 31;
            float4 v = *(const float4*)(src + (size_t)row * CDIM + q * 4);
            *(float4*)(zs + row * ZSTR + q * 4) = v;
        }
    }
    __syncthreads();

    const float maxC2 = __uint_as_float(maxC2u[stage]);
    const float maxC = sqrtf(maxC2);

    for (int j = 0; j < 16; ++j) {
        const int lt = wid * 16 + j;
        const int t = m0 + lt;
        const float* zr = zs + lt * ZSTR;

        float zn2 = 0.f;
#pragma unroll
        for (int q = 0; q < 4; ++q) {
            float v = zr[lane + q * 32];
            zn2 += v * v;
        }
#pragma unroll
        for (int off = 16; off >= 1; off >>= 1)
            zn2 += __shfl_xor_sync(0xffffffffu, zn2, off);

        const float zn = sqrtf(zn2);
        const float margin = ldexpf(zn * maxC, -6) +
                             ldexpf(maxC2 + 2.0f * zn * maxC, -9);
        const float thr = funmap(sdmin[lt]) + margin;

        const __half2* drow = (const __half2*)(D + (size_t)t * CBS);
        unsigned long long best = ~0ull;
        for (int i = 0; i < 16; ++i) {
            float2 v = __half22float2(drow[i * 32 + lane]);
            const int nbase = (i * 32 + lane) * 2;
#pragma unroll
            for (int h = 0; h < 2; ++h) {
                float dv = (h == 0) ? v.x : v.y;
                if (dv <= thr) {
                    const int n = nbase + h;
                    const float* cr = cb + (size_t)n * CDIM;
                    float acc = 0.f;
#pragma unroll 16
                    for (int k = 0; k < 128; ++k)
                        acc = fmaf(zr[k], cr[k], acc);
                    float dd = cbn[n] - 2.0f * acc;
                    unsigned long long key =
                        ((unsigned long long)fmap(dd) << 32) | (unsigned)n;
                    if (key < best) best = key;
                }
            }
        }
#pragma unroll
        for (int off = 16; off >= 1; off >>= 1) {
            unsigned long long o = __shfl_xor_sync(0xffffffffu, best, off);
            if (o < best) best = o;
        }
        const unsigned idx = (unsigned)(best & 0xffffffffu);

        // loss term (sum over CDIM of (ze - zq)^2)
        const float* cq = cb + (size_t)idx * CDIM;
        float s = 0.f;
#pragma unroll
        for (int q = 0; q < 4; ++q) {
            float d = zr[lane + q * 32] - cq[lane + q * 32];
            s += d * d;
        }
#pragma unroll
        for (int off = 16; off >= 1; off >>= 1)
            s += __shfl_xor_sync(0xffffffffu, s, off);
        if (lane == 0) {
            partial[t] = s;
            out_codes[(size_t)t * NCB + stage] = (float)idx;
        }

        // R[t] -= G[idx]  (512 floats; identical single-subtraction arithmetic)
        float4* R4 = (float4*)(R + (size_t)t * ENC);
        const float4* G4 = (const float4*)(G + (size_t)idx * ENC);
#pragma unroll
        for (int q = 0; q < 4; ++q) {
            int o = lane + q * 32;
            float4 r = R4[o], g = G4[o];
            r.x -= g.x; r.y -= g.y; r.z -= g.z; r.w -= g.w;
            R4[o] = r;
        }
    }
}

__global__ void final_loss_kernel(const float* __restrict__ partial, float* __restrict__ out)
{
    __shared__ float s[256];
    float v = 0.f;
    const int per = (NCB * BT_TOK) / 256;   // 1024
    for (int q = 0; q < per; ++q) v += partial[threadIdx.x * per + q];
    s[threadIdx.x] = v;
    __syncthreads();
    for (int st = 128; st > 0; st >>= 1) {
        if (threadIdx.x < st) s[threadIdx.x] += s[threadIdx.x + st];
        __syncthreads();
    }
    if (threadIdx.x == 0)
        out[(size_t)BT_TOK * NCB] = 1.25f * s[0] / (float)((size_t)BT_TOK * CDIM);
}

// ---------------- launch ----------------------------------------------------
extern "C" void kernel_launch(void* const* d_in, const int* in_sizes, int n_in,
                              void* d_out, int out_size)
{
    const float* z    = (const float*)d_in[0];   // (16,2048,768)
    const float* Win  = (const float*)d_in[1];   // (768,512)
    const float* bin  = (const float*)d_in[2];   // (512,)
    const float* cbs  = (const float*)d_in[3];   // (8,1024,128)
    const float* inw  = (const float*)d_in[4];   // (8,512,128)
    const float* outw = (const float*)d_in[5];   // (8,128,512)
    float* out = (float*)d_out;

    float *gR, *gZe, *gCbn, *gLP, *gG;
    __half* gD;
    __nv_bfloat16 *gZeA, *gCbA;
    unsigned* gMx;
    cudaGetSymbolAddress((void**)&gR,   g_R);
    cudaGetSymbolAddress((void**)&gZe,  g_Ze);
    cudaGetSymbolAddress((void**)&gZeA, g_zeA);
    cudaGetSymbolAddress((void**)&gCbA, g_cbA);
    cudaGetSymbolAddress((void**)&gCbn, g_cbnorm);
    cudaGetSymbolAddress((void**)&gMx,  g_maxC2u);
    cudaGetSymbolAddress((void**)&gLP,  g_lossPartial);
    cudaGetSymbolAddress((void**)&gG,   g_G);
    cudaGetSymbolAddress((void**)&gD,   g_D);

    cudaFuncSetAttribute(distFused_kernel,
                         cudaFuncAttributeMaxDynamicSharedMemorySize, P1_TOT);

    // 1. residual = z @ W_in + b_in
    sgemm4<true, false><<<dim3(BT_TOK / 128, ENC / 128, 1), 256>>>(
        z, Win, gR, bin, nullptr, IN_DIM, ENC, 0, 0, 0);

    // 2. codebook norms (+ per-stage max) + bf16 a-planes
    norm_kernel<<<(NCB * CBS * 32) / 256, 256>>>(cbs, gCbn, gMx, NCB * CBS);
    split_cb_kernel<<<(NCB * CBS * CDIM) / 256, 256>>>(cbs, gCbA);

    // 3. dec tables: G_i = cb_i @ out_w_i (batched over blockIdx.z)
    sgemm4<false, false><<<dim3(CBS / 128, ENC / 128, NCB), 256>>>(
        cbs, outw, gG, nullptr, nullptr, CDIM, ENC,
        (size_t)CBS * CDIM, (size_t)CDIM * ENC, (size_t)CBS * ENC);

    for (int i = 0; i < NCB; ++i) {
        const float* cb_i = cbs + (size_t)i * CBS * CDIM;

        // z_e = R @ in_w[i]  (fp32 + bf16 a-plane)
        sgemm4<false, true><<<dim3(BT_TOK / 128, CDIM / 128, 1), 256>>>(
            gR, inw + (size_t)i * ENC * CDIM, gZe, nullptr, gZeA, ENC, CDIM, 0, 0, 0);

        // fused: approx distances + certified exact argmin + codes/loss/R-update
        distFused_kernel<<<BT_TOK / 128, 256, P1_TOT>>>(
            gZeA, gCbA + (size_t)i * CBS * CDIM, gCbn + (size_t)i * CBS, gD,
            gZe, cb_i, gG + (size_t)i * CBS * ENC, gMx, i,
            out, gLP + (size_t)i * BT_TOK, gR);
    }

    final_loss_kernel<<<1, 256>>>(gLP, out);
}

// round 13
// speedup vs baseline: 1.2673x; 1.2673x over previous
#include <cuda_runtime.h>
#include <cuda_bf16.h>
#include <cuda_fp16.h>
#include <cstdint>

#define BT_TOK 32768      // B*T = 16*2048
#define IN_DIM 768
#define ENC 512
#define CDIM 128
#define NCB 8
#define CBS 1024

// ---------------- scratch (static device globals; no allocations) ----------
__device__ float g_R[BT_TOK * ENC];                    // residual (64MB)
__device__ float g_Ze[BT_TOK * CDIM];                  // z_e fp32 (16MB)
__device__ __nv_bfloat16 g_zeA[(size_t)BT_TOK * CDIM]; // ze bf16 a-plane (8MB)
__device__ __nv_bfloat16 g_cbA[(size_t)NCB * CBS * CDIM]; // cb a-plane (2MB)
__device__ __half g_D[(size_t)BT_TOK * CBS];           // approx distances (64MB)
__device__ unsigned g_idx[BT_TOK];                     // winning code per token
__device__ unsigned g_dminU[BT_TOK];                   // per-token min (monotonic bits)
__device__ float g_cbnorm[NCB * CBS];                  // ||c||^2
__device__ unsigned g_maxC2u[NCB];                     // max ||c||^2 (bits), zero-init
__device__ float g_G[NCB * CBS * ENC];                 // cb @ out_w tables (16MB)
__device__ float g_lossPartial[NCB * BT_TOK];          // deterministic partials

// ---------------- helpers ----------------------------------------------------
__device__ __forceinline__ void cp16(uint32_t smem, const void* gmem) {
    asm volatile("cp.async.cg.shared.global [%0], [%1], 16;\n" :: "r"(smem), "l"(gmem));
}
__device__ __forceinline__ void cp16p(void* smem, const void* gmem) {
    cp16((uint32_t)__cvta_generic_to_shared(smem), gmem);
}
#define CP_COMMIT asm volatile("cp.async.commit_group;\n" ::)
#define CP_WAIT0  asm volatile("cp.async.wait_group 0;\n" ::)
#define CP_WAIT1  asm volatile("cp.async.wait_group 1;\n" ::)

__device__ __forceinline__ unsigned long long pack2(float lo, float hi) {
    unsigned long long r;
    asm("mov.b64 %0, {%1, %2};" : "=l"(r) : "f"(lo), "f"(hi));
    return r;
}
__device__ __forceinline__ void unpack2(float& lo, float& hi, unsigned long long v) {
    asm("mov.b64 {%0, %1}, %2;" : "=f"(lo), "=f"(hi) : "l"(v));
}
__device__ __forceinline__ void fma2(unsigned long long& d, unsigned long long a,
                                     unsigned long long b) {
    asm("fma.rn.f32x2 %0, %1, %2, %0;" : "+l"(d) : "l"(a), "l"(b));
}

__device__ __forceinline__ unsigned fmap(float x) {    // monotonic float->uint
    unsigned ib = __float_as_uint(x);
    return ib ^ ((ib & 0x80000000u) ? 0xffffffffu : 0x80000000u);
}
__device__ __forceinline__ float funmap(unsigned u) {
    unsigned ib = (u & 0x80000000u) ? (u ^ 0x80000000u) : ~u;
    return __uint_as_float(ib);
}

#define LDMX4(r, addr) \
    asm volatile("ldmatrix.sync.aligned.m8n8.x4.shared.b16 {%0,%1,%2,%3}, [%4];" \
                 : "=r"((r)[0]), "=r"((r)[1]), "=r"((r)[2]), "=r"((r)[3]) : "r"(addr))
#define LDMX2(r, addr) \
    asm volatile("ldmatrix.sync.aligned.m8n8.x2.shared.b16 {%0,%1}, [%2];" \
                 : "=r"((r)[0]), "=r"((r)[1]) : "r"(addr))
#define MMA16816(c, a, b) \
    asm volatile("mma.sync.aligned.m16n8k16.row.col.f32.bf16.bf16.f32 " \
                 "{%0,%1,%2,%3}, {%4,%5,%6,%7}, {%8,%9}, {%0,%1,%2,%3};" \
                 : "+f"((c)[0]), "+f"((c)[1]), "+f"((c)[2]), "+f"((c)[3]) \
                 : "r"((a)[0]), "r"((a)[1]), "r"((a)[2]), "r"((a)[3]), \
                   "r"((b)[0]), "r"((b)[1]))

// ---------------- SGEMM: 128x128 tile, BK=16, smem DB, FFMA2 core ----------
// C = A @ B (+bias). SPLIT: also emit bf16 a-plane of C + reset dminU.
// UPD: A-row := R[m] - G[idx[m]] (bit-identical single subtraction; the
//      updated row is written back to R and used as the GEMM operand).
// Per-output fp32 accumulation chain: k strictly ascending (bit-identical R1-R11).
template<bool BIAS, bool SPLIT, bool UPD>
__global__ __launch_bounds__(256, 2) void sgemm4(
    const float* __restrict__ A, const float* __restrict__ B,
    float* __restrict__ C, const float* __restrict__ bias,
    __nv_bfloat16* __restrict__ splitOut,
    const unsigned* __restrict__ gidx, const float* __restrict__ Gtab,
    float* __restrict__ Rw, unsigned* __restrict__ dminU,
    int K, int N, size_t strA, size_t strB, size_t strC)
{
    __shared__ float As[2][16][128];
    __shared__ float Bs[2][16][128];
    A += (size_t)blockIdx.z * strA;
    B += (size_t)blockIdx.z * strB;
    C += (size_t)blockIdx.z * strC;
    const int tid = threadIdx.x;
    const int tx = tid & 15, ty = tid >> 4;
    const int m0 = blockIdx.x * 128;
    const int n0 = blockIdx.y * 128;

    if (SPLIT && tid < 128) dminU[m0 + tid] = 0xffffffffu;

    const int ar = tid & 127;
    const int ah = (tid >> 7) * 8;
    const int br = tid >> 4;
    const int bc = (tid & 15) * 4;

    const float* aptr = A + (size_t)(m0 + ar) * K;
    const float* gptr = nullptr;
    float* rw = nullptr;
    if (UPD) {
        unsigned iv = gidx[m0 + ar];
        gptr = Gtab + (size_t)iv * ENC;
        rw = Rw + (size_t)(m0 + ar) * K;
    }
    const float* bptr = B + n0;

    const int T = K >> 4;

    float4 av0 = *(const float4*)(aptr + ah);
    float4 av1 = *(const float4*)(aptr + ah + 4);
    if (UPD) {
        float4 g0 = *(const float4*)(gptr + ah);
        float4 g1 = *(const float4*)(gptr + ah + 4);
        av0.x -= g0.x; av0.y -= g0.y; av0.z -= g0.z; av0.w -= g0.w;
        av1.x -= g1.x; av1.y -= g1.y; av1.z -= g1.z; av1.w -= g1.w;
        *(float4*)(rw + ah) = av0;
        *(float4*)(rw + ah + 4) = av1;
    }
    cp16p(&Bs[0][br][bc],      bptr + (size_t)br * N + bc);
    cp16p(&Bs[0][br][bc + 64], bptr + (size_t)br * N + bc + 64);
    As[0][ah + 0][ar] = av0.x; As[0][ah + 1][ar] = av0.y;
    As[0][ah + 2][ar] = av0.z; As[0][ah + 3][ar] = av0.w;
    As[0][ah + 4][ar] = av1.x; As[0][ah + 5][ar] = av1.y;
    As[0][ah + 6][ar] = av1.z; As[0][ah + 7][ar] = av1.w;
    CP_COMMIT;
    CP_WAIT0;
    __syncthreads();

    unsigned long long acc2[8][4];
#pragma unroll
    for (int i = 0; i < 8; ++i)
#pragma unroll
        for (int j = 0; j < 4; ++j) acc2[i][j] = 0ull;

    for (int t = 0; t < T; ++t) {
        const int buf = t & 1;
        const bool pf = (t + 1 < T);
        const int kn = (t + 1) << 4;
        if (pf) {
            av0 = *(const float4*)(aptr + kn + ah);
            av1 = *(const float4*)(aptr + kn + ah + 4);
            if (UPD) {
                float4 g0 = *(const float4*)(gptr + kn + ah);
                float4 g1 = *(const float4*)(gptr + kn + ah + 4);
                av0.x -= g0.x; av0.y -= g0.y; av0.z -= g0.z; av0.w -= g0.w;
                av1.x -= g1.x; av1.y -= g1.y; av1.z -= g1.z; av1.w -= g1.w;
                *(float4*)(rw + kn + ah) = av0;
                *(float4*)(rw + kn + ah + 4) = av1;
            }
            cp16p(&Bs[buf ^ 1][br][bc],      bptr + (size_t)(kn + br) * N + bc);
            cp16p(&Bs[buf ^ 1][br][bc + 64], bptr + (size_t)(kn + br) * N + bc + 64);
            CP_COMMIT;
        }
#pragma unroll
        for (int k = 0; k < 16; ++k) {
            float a[8];
            *(float4*)(a)     = *(const float4*)&As[buf][k][ty * 8];
            *(float4*)(a + 4) = *(const float4*)&As[buf][k][ty * 8 + 4];
            float4 b0 = *(const float4*)&Bs[buf][k][tx * 8];
            float4 b1 = *(const float4*)&Bs[buf][k][tx * 8 + 4];
            unsigned long long bb[4];
            bb[0] = pack2(b0.x, b0.y); bb[1] = pack2(b0.z, b0.w);
            bb[2] = pack2(b1.x, b1.y); bb[3] = pack2(b1.z, b1.w);
#pragma unroll
            for (int i = 0; i < 8; ++i) {
                unsigned long long ai = pack2(a[i], a[i]);
#pragma unroll
                for (int j = 0; j < 4; ++j) fma2(acc2[i][j], ai, bb[j]);
            }
        }
        if (pf) {
            As[buf ^ 1][ah + 0][ar] = av0.x; As[buf ^ 1][ah + 1][ar] = av0.y;
            As[buf ^ 1][ah + 2][ar] = av0.z; As[buf ^ 1][ah + 3][ar] = av0.w;
            As[buf ^ 1][ah + 4][ar] = av1.x; As[buf ^ 1][ah + 5][ar] = av1.y;
            As[buf ^ 1][ah + 6][ar] = av1.z; As[buf ^ 1][ah + 7][ar] = av1.w;
            CP_WAIT0;
            __syncthreads();
        }
    }

#pragma unroll
    for (int i = 0; i < 8; ++i) {
        float c[8];
#pragma unroll
        for (int j = 0; j < 4; ++j) unpack2(c[2 * j], c[2 * j + 1], acc2[i][j]);
        int m = m0 + ty * 8 + i;
        float* crow = C + (size_t)m * N + n0 + tx * 8;
        if (BIAS) {
#pragma unroll
            for (int j = 0; j < 8; ++j) crow[j] = c[j] + bias[n0 + tx * 8 + j];
        } else {
#pragma unroll
            for (int j = 0; j < 8; ++j) crow[j] = c[j];
        }
        if (SPLIT) {
            __align__(16) __nv_bfloat16 pa[8];
#pragma unroll
            for (int j = 0; j < 8; ++j) pa[j] = __float2bfloat16(c[j]);
            *(uint4*)(splitOut + (size_t)m * CDIM + n0 + tx * 8) = *(const uint4*)pa;
        }
    }
}

// ---------------- codebook a-plane + norms ----------------------------------
__global__ void split_cb_kernel(const float* __restrict__ cb,
                                __nv_bfloat16* __restrict__ out)
{
    size_t i = (size_t)blockIdx.x * blockDim.x + threadIdx.x;
    if (i >= (size_t)NCB * CBS * CDIM) return;
    out[i] = __float2bfloat16(cb[i]);
}

// norms + per-stage max||c||^2 (atomicMax on positive-float bits: order-free)
__global__ void norm_kernel(const float* __restrict__ cb, float* __restrict__ out,
                            unsigned* __restrict__ maxC2u, int rows)
{
    int w = (blockIdx.x * blockDim.x + threadIdx.x) >> 5;
    int lane = threadIdx.x & 31;
    if (w >= rows) return;
    const float* r = cb + (size_t)w * CDIM;
    float s = 0.f;
#pragma unroll
    for (int q = 0; q < 4; ++q) { float v = r[lane + q * 32]; s += v * v; }
#pragma unroll
    for (int off = 16; off >= 1; off >>= 1) s += __shfl_xor_sync(0xffffffffu, s, off);
    if (lane == 0) {
        out[w] = s;
        atomicMax(&maxC2u[w >> 10], __float_as_uint(s));
    }
}

// ---------------- phase 1: approx distances, single bf16 pass ---------------
// Per CTA: 128 tokens x 1024 codes; A = bf16(ze) resident; B = 64-code chunks
// double-buffered. d~ = ||c||^2 - 2*(a.a) written fp16; per-row running min of
// the SAME fp16-rounded values -> global atomicMin (order-free => exact dmin).
#define PSTR 272                        // smem row stride (256B data + 16 pad)
#define P1_B (128 * PSTR)               // 34816
#define P1_BBUF (64 * PSTR)             // 17408
#define P1_TOT (P1_B + 2 * P1_BBUF)     // 69632 dynamic smem

__global__ __launch_bounds__(256) void distApprox_kernel(
    const __nv_bfloat16* __restrict__ zeA,   // [BT_TOK][128]
    const __nv_bfloat16* __restrict__ cbA,   // stage base [CBS][128]
    const float* __restrict__ cbn,           // stage base [CBS]
    __half* __restrict__ D,                  // [BT_TOK][CBS]
    unsigned* __restrict__ dminU)            // per-token min bits
{
    extern __shared__ char smem[];
    const uint32_t sb = (uint32_t)__cvta_generic_to_shared(smem);
    const int tid = threadIdx.x;
    const int lane = tid & 31, wid = tid >> 5;
    const int rowband = wid & 3;
    const int colhalf = wid >> 2;
    const int gid = lane >> 2, tig = lane & 3;
    const int m0 = blockIdx.x * 128;

    {
        const __nv_bfloat16* src = zeA + (size_t)m0 * CDIM;
#pragma unroll
        for (int it = 0; it < 8; ++it) {
            int idx = tid + it * 256;
            int row = idx >> 4, piece = idx & 15;
            cp16(sb + row * PSTR + piece * 16, src + (size_t)row * CDIM + piece * 8);
        }
    }
    CP_COMMIT;
    {
#pragma unroll
        for (int it = 0; it < 4; ++it) {
            int idx = tid + it * 256;
            int row = idx >> 4, piece = idx & 15;
            cp16(sb + P1_B + row * PSTR + piece * 16,
                 cbA + (size_t)row * CDIM + piece * 8);
        }
    }
    CP_COMMIT;

    const uint32_t aBase = sb + (rowband * 32 + (lane & 15)) * PSTR + (lane >> 4) * 16;
    const uint32_t bLaneOff = (colhalf * 32 + (lane & 7)) * PSTR +
                              ((lane >> 3) & 1) * 16;

    float c[2][4][4];
#pragma unroll
    for (int rt = 0; rt < 2; ++rt)
#pragma unroll
        for (int ct = 0; ct < 4; ++ct)
#pragma unroll
            for (int v = 0; v < 4; ++v) c[rt][ct][v] = 0.f;

    float rmin[4] = {3.4e38f, 3.4e38f, 3.4e38f, 3.4e38f};

    for (int nc = 0; nc < 16; ++nc) {
        const int buf = nc & 1;
        if (nc + 1 < 16) {
            const __nv_bfloat16* src = cbA + (size_t)(nc + 1) * 64 * CDIM;
            const uint32_t dst = sb + P1_B + (buf ^ 1) * P1_BBUF;
#pragma unroll
            for (int it = 0; it < 4; ++it) {
                int idx = tid + it * 256;
                int row = idx >> 4, piece = idx & 15;
                cp16(dst + row * PSTR + piece * 16,
                     src + (size_t)row * CDIM + piece * 8);
            }
            CP_COMMIT;
            CP_WAIT1;
        } else {
            CP_WAIT0;
        }
        __syncthreads();

        const uint32_t bBase = sb + P1_B + buf * P1_BBUF + bLaneOff;
#pragma unroll
        for (int kc = 0; kc < 2; ++kc) {
#pragma unroll
            for (int ks = 0; ks < 4; ++ks) {
                const uint32_t off = kc * 128 + ks * 32;
                uint32_t a[2][4];
                LDMX4(a[0], aBase + off);
                LDMX4(a[1], aBase + 16 * PSTR + off);
                uint32_t b[4][2];
#pragma unroll
                for (int ct = 0; ct < 4; ++ct)
                    LDMX2(b[ct], bBase + ct * 8 * PSTR + off);
#pragma unroll
                for (int rt = 0; rt < 2; ++rt)
#pragma unroll
                    for (int ct = 0; ct < 4; ++ct)
                        MMA16816(c[rt][ct], a[rt], b[ct]);
            }
        }

        {
            const int colb = nc * 64 + colhalf * 32;
#pragma unroll
            for (int rt = 0; rt < 2; ++rt) {
                const int row = m0 + rowband * 32 + rt * 16 + gid;
                __half2* d0 = (__half2*)(D + (size_t)row * CBS);
                __half2* d1 = (__half2*)(D + (size_t)(row + 8) * CBS);
#pragma unroll
                for (int ct = 0; ct < 4; ++ct) {
                    const int col = colb + ct * 8 + tig * 2;
                    const float cn0 = cbn[col], cn1 = cbn[col + 1];
                    __half2 h0 = __floats2half2_rn(cn0 - 2.0f * c[rt][ct][0],
                                                   cn1 - 2.0f * c[rt][ct][1]);
                    __half2 h1 = __floats2half2_rn(cn0 - 2.0f * c[rt][ct][2],
                                                   cn1 - 2.0f * c[rt][ct][3]);
                    d0[col >> 1] = h0;
                    d1[col >> 1] = h1;
                    float2 f0 = __half22float2(h0);
                    float2 f1 = __half22float2(h1);
                    rmin[rt * 2]     = fminf(rmin[rt * 2],     fminf(f0.x, f0.y));
                    rmin[rt * 2 + 1] = fminf(rmin[rt * 2 + 1], fminf(f1.x, f1.y));
                    c[rt][ct][0] = 0.f; c[rt][ct][1] = 0.f;
                    c[rt][ct][2] = 0.f; c[rt][ct][3] = 0.f;
                }
            }
        }
        __syncthreads();
    }

#pragma unroll
    for (int rt = 0; rt < 2; ++rt) {
        const int row = m0 + rowband * 32 + rt * 16 + gid;
        atomicMin(&dminU[row],     fmap(rmin[rt * 2]));
        atomicMin(&dminU[row + 8], fmap(rmin[rt * 2 + 1]));
    }
}

// ---------------- phase 2: certified rescore + codes + loss + idx -----------
// Per warp = 1 token. thr = dmin + margin (same margin & dmin values as R11);
// rescore candidates with the exact fp32 chain (acc=fma(ze_k,cb_k,acc) k asc;
// d = cbn - 2*acc); key-min == full fp32 argmin. Then codes + loss + g_idx.
__global__ __launch_bounds__(256) void argminExact_kernel(
    const float* __restrict__ Ze, const __half* __restrict__ D,
    const float* __restrict__ cb, const float* __restrict__ cbn,
    const unsigned* __restrict__ maxC2u, int stage,
    const unsigned* __restrict__ dminU,
    unsigned* __restrict__ idxOut, float* __restrict__ out_codes,
    float* __restrict__ partial)
{
    __shared__ float zrow[8][128];
    const int lane = threadIdx.x & 31, wid = threadIdx.x >> 5;
    const int t = blockIdx.x * 8 + wid;

    const float* zep = Ze + (size_t)t * CDIM;
    float zn2 = 0.f;
#pragma unroll
    for (int q = 0; q < 4; ++q) {
        float v = zep[lane + q * 32];
        zrow[wid][lane + q * 32] = v;
        zn2 += v * v;
    }
#pragma unroll
    for (int off = 16; off >= 1; off >>= 1)
        zn2 += __shfl_xor_sync(0xffffffffu, zn2, off);
    __syncwarp();

    const float maxC2 = __uint_as_float(maxC2u[stage]);
    const float zn = sqrtf(zn2), maxC = sqrtf(maxC2);
    const float margin = ldexpf(zn * maxC, -6) +
                         ldexpf(maxC2 + 2.0f * zn * maxC, -9);
    const float thr = funmap(dminU[t]) + margin;

    const __half2* drow = (const __half2*)(D + (size_t)t * CBS);
    unsigned long long best = ~0ull;
    for (int i = 0; i < 16; ++i) {
        float2 v = __half22float2(drow[i * 32 + lane]);
        const int nbase = (i * 32 + lane) * 2;
#pragma unroll
        for (int h = 0; h < 2; ++h) {
            float dv = (h == 0) ? v.x : v.y;
            if (dv <= thr) {
                const int n = nbase + h;
                const float* cr = cb + (size_t)n * CDIM;
                float acc = 0.f;
#pragma unroll 16
                for (int k = 0; k < 128; ++k)
                    acc = fmaf(zrow[wid][k], cr[k], acc);
                float dd = cbn[n] - 2.0f * acc;
                unsigned long long key =
                    ((unsigned long long)fmap(dd) << 32) | (unsigned)n;
                if (key < best) best = key;
            }
        }
    }
#pragma unroll
    for (int off = 16; off >= 1; off >>= 1) {
        unsigned long long o = __shfl_xor_sync(0xffffffffu, best, off);
        if (o < best) best = o;
    }
    const unsigned idx = (unsigned)(best & 0xffffffffu);

    // loss: sum over CDIM of (ze - zq)^2
    const float* cq = cb + (size_t)idx * CDIM;
    float s = 0.f;
#pragma unroll
    for (int q = 0; q < 4; ++q) {
        float d = zrow[wid][lane + q * 32] - cq[lane + q * 32];
        s += d * d;
    }
#pragma unroll
    for (int off = 16; off >= 1; off >>= 1)
        s += __shfl_xor_sync(0xffffffffu, s, off);

    if (lane == 0) {
        idxOut[t] = idx;
        partial[t] = s;
        out_codes[(size_t)t * NCB + stage] = (float)idx;
    }
}

__global__ void final_loss_kernel(const float* __restrict__ partial, float* __restrict__ out)
{
    __shared__ float s[256];
    float v = 0.f;
    const int per = (NCB * BT_TOK) / 256;   // 1024
    for (int q = 0; q < per; ++q) v += partial[threadIdx.x * per + q];
    s[threadIdx.x] = v;
    __syncthreads();
    for (int st = 128; st > 0; st >>= 1) {
        if (threadIdx.x < st) s[threadIdx.x] += s[threadIdx.x + st];
        __syncthreads();
    }
    if (threadIdx.x == 0)
        out[(size_t)BT_TOK * NCB] = 1.25f * s[0] / (float)((size_t)BT_TOK * CDIM);
}

// ---------------- launch ----------------------------------------------------
extern "C" void kernel_launch(void* const* d_in, const int* in_sizes, int n_in,
                              void* d_out, int out_size)
{
    const float* z    = (const float*)d_in[0];   // (16,2048,768)
    const float* Win  = (const float*)d_in[1];   // (768,512)
    const float* bin  = (const float*)d_in[2];   // (512,)
    const float* cbs  = (const float*)d_in[3];   // (8,1024,128)
    const float* inw  = (const float*)d_in[4];   // (8,512,128)
    const float* outw = (const float*)d_in[5];   // (8,128,512)
    float* out = (float*)d_out;

    float *gR, *gZe, *gCbn, *gLP, *gG;
    __half* gD;
    __nv_bfloat16 *gZeA, *gCbA;
    unsigned *gMx, *gIdx, *gDm;
    cudaGetSymbolAddress((void**)&gR,   g_R);
    cudaGetSymbolAddress((void**)&gZe,  g_Ze);
    cudaGetSymbolAddress((void**)&gZeA, g_zeA);
    cudaGetSymbolAddress((void**)&gCbA, g_cbA);
    cudaGetSymbolAddress((void**)&gCbn, g_cbnorm);
    cudaGetSymbolAddress((void**)&gMx,  g_maxC2u);
    cudaGetSymbolAddress((void**)&gLP,  g_lossPartial);
    cudaGetSymbolAddress((void**)&gG,   g_G);
    cudaGetSymbolAddress((void**)&gD,   g_D);
    cudaGetSymbolAddress((void**)&gIdx, g_idx);
    cudaGetSymbolAddress((void**)&gDm,  g_dminU);

    cudaFuncSetAttribute(distApprox_kernel,
                         cudaFuncAttributeMaxDynamicSharedMemorySize, P1_TOT);

    // 1. residual = z @ W_in + b_in
    sgemm4<true, false, false><<<dim3(BT_TOK / 128, ENC / 128, 1), 256>>>(
        z, Win, gR, bin, nullptr, nullptr, nullptr, nullptr, nullptr,
        IN_DIM, ENC, 0, 0, 0);

    // 2. codebook norms (+ per-stage max) + bf16 a-planes
    norm_kernel<<<(NCB * CBS * 32) / 256, 256>>>(cbs, gCbn, gMx, NCB * CBS);
    split_cb_kernel<<<(NCB * CBS * CDIM) / 256, 256>>>(cbs, gCbA);

    // 3. dec tables: G_i = cb_i @ out_w_i (batched over blockIdx.z)
    sgemm4<false, false, false><<<dim3(CBS / 128, ENC / 128, NCB), 256>>>(
        cbs, outw, gG, nullptr, nullptr, nullptr, nullptr, nullptr, nullptr,
        CDIM, ENC, (size_t)CBS * CDIM, (size_t)CDIM * ENC, (size_t)CBS * ENC);

    for (int i = 0; i < NCB; ++i) {
        const float* cb_i = cbs + (size_t)i * CBS * CDIM;

        // z_e = (R - G_{i-1}[idx]) @ in_w[i]; writes updated R back (i>0).
        if (i == 0) {
            sgemm4<false, true, false><<<dim3(BT_TOK / 128, 1, 1), 256>>>(
                gR, inw, gZe, nullptr, gZeA, nullptr, nullptr, nullptr, gDm,
                ENC, CDIM, 0, 0, 0);
        } else {
            sgemm4<false, true, true><<<dim3(BT_TOK / 128, 1, 1), 256>>>(
                gR, inw + (size_t)i * ENC * CDIM, gZe, nullptr, gZeA,
                gIdx, gG + (size_t)(i - 1) * CBS * ENC, gR, gDm,
                ENC, CDIM, 0, 0, 0);
        }

        // phase 1: approx distances + per-token dmin
        distApprox_kernel<<<BT_TOK / 128, 256, P1_TOT>>>(
            gZeA, gCbA + (size_t)i * CBS * CDIM, gCbn + (size_t)i * CBS, gD, gDm);

        // phase 2: certified exact argmin + codes + loss + idx
        argminExact_kernel<<<BT_TOK / 8, 256>>>(
            gZe, gD, cb_i, gCbn + (size_t)i * CBS, gMx, i, gDm,
            gIdx, out, gLP + (size_t)i * BT_TOK);
    }

    final_loss_kernel<<<1, 256>>>(gLP, out);
}

// round 14
// speedup vs baseline: 1.2780x; 1.0085x over previous
#include <cuda_runtime.h>
#include <cuda_bf16.h>
#include <cuda_fp16.h>
#include <cstdint>

#define BT_TOK 32768      // B*T = 16*2048
#define IN_DIM 768
#define ENC 512
#define CDIM 128
#define NCB 8
#define CBS 1024

// ---------------- scratch (static device globals; no allocations) ----------
__device__ float g_R[BT_TOK * ENC];                    // residual (64MB)
__device__ float g_Ze[BT_TOK * CDIM];                  // z_e fp32 (16MB)
__device__ __nv_bfloat16 g_zeA[(size_t)BT_TOK * CDIM]; // ze bf16 a-plane (8MB)
__device__ __nv_bfloat16 g_cbA[(size_t)NCB * CBS * CDIM]; // cb a-plane (2MB)
__device__ __half g_D[(size_t)BT_TOK * CBS];           // approx distances (64MB)
__device__ unsigned g_dminU[BT_TOK];                   // per-token min (monotonic bits)
__device__ float g_cbnorm[NCB * CBS];                  // ||c||^2
__device__ unsigned g_maxC2u[NCB];                     // max ||c||^2 (bits), zero-init
__device__ float g_G[NCB * CBS * ENC];                 // cb @ out_w tables (16MB)
__device__ float g_lossPartial[NCB * BT_TOK];          // deterministic partials

// ---------------- helpers ----------------------------------------------------
__device__ __forceinline__ void cp16(uint32_t smem, const void* gmem) {
    asm volatile("cp.async.cg.shared.global [%0], [%1], 16;\n" :: "r"(smem), "l"(gmem));
}
__device__ __forceinline__ void cp16p(void* smem, const void* gmem) {
    cp16((uint32_t)__cvta_generic_to_shared(smem), gmem);
}
#define CP_COMMIT asm volatile("cp.async.commit_group;\n" ::)
#define CP_WAIT0  asm volatile("cp.async.wait_group 0;\n" ::)
#define CP_WAIT1  asm volatile("cp.async.wait_group 1;\n" ::)

__device__ __forceinline__ unsigned long long pack2(float lo, float hi) {
    unsigned long long r;
    asm("mov.b64 %0, {%1, %2};" : "=l"(r) : "f"(lo), "f"(hi));
    return r;
}
__device__ __forceinline__ void unpack2(float& lo, float& hi, unsigned long long v) {
    asm("mov.b64 {%0, %1}, %2;" : "=f"(lo), "=f"(hi) : "l"(v));
}
__device__ __forceinline__ void fma2(unsigned long long& d, unsigned long long a,
                                     unsigned long long b) {
    asm("fma.rn.f32x2 %0, %1, %2, %0;" : "+l"(d) : "l"(a), "l"(b));
}

__device__ __forceinline__ unsigned fmap(float x) {    // monotonic float->uint
    unsigned ib = __float_as_uint(x);
    return ib ^ ((ib & 0x80000000u) ? 0xffffffffu : 0x80000000u);
}
__device__ __forceinline__ float funmap(unsigned u) {
    unsigned ib = (u & 0x80000000u) ? (u ^ 0x80000000u) : ~u;
    return __uint_as_float(ib);
}

#define LDMX4(r, addr) \
    asm volatile("ldmatrix.sync.aligned.m8n8.x4.shared.b16 {%0,%1,%2,%3}, [%4];" \
                 : "=r"((r)[0]), "=r"((r)[1]), "=r"((r)[2]), "=r"((r)[3]) : "r"(addr))
#define LDMX2(r, addr) \
    asm volatile("ldmatrix.sync.aligned.m8n8.x2.shared.b16 {%0,%1}, [%2];" \
                 : "=r"((r)[0]), "=r"((r)[1]) : "r"(addr))
#define MMA16816(c, a, b) \
    asm volatile("mma.sync.aligned.m16n8k16.row.col.f32.bf16.bf16.f32 " \
                 "{%0,%1,%2,%3}, {%4,%5,%6,%7}, {%8,%9}, {%0,%1,%2,%3};" \
                 : "+f"((c)[0]), "+f"((c)[1]), "+f"((c)[2]), "+f"((c)[3]) \
                 : "r"((a)[0]), "r"((a)[1]), "r"((a)[2]), "r"((a)[3]), \
                   "r"((b)[0]), "r"((b)[1]))

// ---------------- SGEMM: 128x128 tile, BK=16, smem DB, FFMA2 core ----------
// C = A @ B (+bias). SPLIT: also emit bf16 a-plane of C + reset dminU.
// Per-output fp32 accumulation chain: k strictly ascending (bit-identical R1-R13).
template<bool BIAS, bool SPLIT>
__global__ __launch_bounds__(256, 2) void sgemm4(
    const float* __restrict__ A, const float* __restrict__ B,
    float* __restrict__ C, const float* __restrict__ bias,
    __nv_bfloat16* __restrict__ splitOut, unsigned* __restrict__ dminU,
    int K, int N, size_t strA, size_t strB, size_t strC)
{
    __shared__ float As[2][16][128];
    __shared__ float Bs[2][16][128];
    A += (size_t)blockIdx.z * strA;
    B += (size_t)blockIdx.z * strB;
    C += (size_t)blockIdx.z * strC;
    const int tid = threadIdx.x;
    const int tx = tid & 15, ty = tid >> 4;
    const int m0 = blockIdx.x * 128;
    const int n0 = blockIdx.y * 128;

    if (SPLIT && tid < 128) dminU[m0 + tid] = 0xffffffffu;

    const int ar = tid & 127;
    const int ah = (tid >> 7) * 8;
    const int br = tid >> 4;
    const int bc = (tid & 15) * 4;

    const float* aptr = A + (size_t)(m0 + ar) * K;
    const float* bptr = B + n0;

    const int T = K >> 4;

    float4 av0 = *(const float4*)(aptr + ah);
    float4 av1 = *(const float4*)(aptr + ah + 4);
    cp16p(&Bs[0][br][bc],      bptr + (size_t)br * N + bc);
    cp16p(&Bs[0][br][bc + 64], bptr + (size_t)br * N + bc + 64);
    As[0][ah + 0][ar] = av0.x; As[0][ah + 1][ar] = av0.y;
    As[0][ah + 2][ar] = av0.z; As[0][ah + 3][ar] = av0.w;
    As[0][ah + 4][ar] = av1.x; As[0][ah + 5][ar] = av1.y;
    As[0][ah + 6][ar] = av1.z; As[0][ah + 7][ar] = av1.w;
    CP_COMMIT;
    CP_WAIT0;
    __syncthreads();

    unsigned long long acc2[8][4];
#pragma unroll
    for (int i = 0; i < 8; ++i)
#pragma unroll
        for (int j = 0; j < 4; ++j) acc2[i][j] = 0ull;

    for (int t = 0; t < T; ++t) {
        const int buf = t & 1;
        const bool pf = (t + 1 < T);
        const int kn = (t + 1) << 4;
        if (pf) {
            av0 = *(const float4*)(aptr + kn + ah);
            av1 = *(const float4*)(aptr + kn + ah + 4);
            cp16p(&Bs[buf ^ 1][br][bc],      bptr + (size_t)(kn + br) * N + bc);
            cp16p(&Bs[buf ^ 1][br][bc + 64], bptr + (size_t)(kn + br) * N + bc + 64);
            CP_COMMIT;
        }
#pragma unroll
        for (int k = 0; k < 16; ++k) {
            float a[8];
            *(float4*)(a)     = *(const float4*)&As[buf][k][ty * 8];
            *(float4*)(a + 4) = *(const float4*)&As[buf][k][ty * 8 + 4];
            float4 b0 = *(const float4*)&Bs[buf][k][tx * 8];
            float4 b1 = *(const float4*)&Bs[buf][k][tx * 8 + 4];
            unsigned long long bb[4];
            bb[0] = pack2(b0.x, b0.y); bb[1] = pack2(b0.z, b0.w);
            bb[2] = pack2(b1.x, b1.y); bb[3] = pack2(b1.z, b1.w);
#pragma unroll
            for (int i = 0; i < 8; ++i) {
                unsigned long long ai = pack2(a[i], a[i]);
#pragma unroll
                for (int j = 0; j < 4; ++j) fma2(acc2[i][j], ai, bb[j]);
            }
        }
        if (pf) {
            As[buf ^ 1][ah + 0][ar] = av0.x; As[buf ^ 1][ah + 1][ar] = av0.y;
            As[buf ^ 1][ah + 2][ar] = av0.z; As[buf ^ 1][ah + 3][ar] = av0.w;
            As[buf ^ 1][ah + 4][ar] = av1.x; As[buf ^ 1][ah + 5][ar] = av1.y;
            As[buf ^ 1][ah + 6][ar] = av1.z; As[buf ^ 1][ah + 7][ar] = av1.w;
            CP_WAIT0;
            __syncthreads();
        }
    }

#pragma unroll
    for (int i = 0; i < 8; ++i) {
        float c[8];
#pragma unroll
        for (int j = 0; j < 4; ++j) unpack2(c[2 * j], c[2 * j + 1], acc2[i][j]);
        int m = m0 + ty * 8 + i;
        float* crow = C + (size_t)m * N + n0 + tx * 8;
        if (BIAS) {
#pragma unroll
            for (int j = 0; j < 8; ++j) crow[j] = c[j] + bias[n0 + tx * 8 + j];
        } else {
#pragma unroll
            for (int j = 0; j < 8; ++j) crow[j] = c[j];
        }
        if (SPLIT) {
            __align__(16) __nv_bfloat16 pa[8];
#pragma unroll
            for (int j = 0; j < 8; ++j) pa[j] = __float2bfloat16(c[j]);
            *(uint4*)(splitOut + (size_t)m * CDIM + n0 + tx * 8) = *(const uint4*)pa;
        }
    }
}

// ---------------- codebook a-plane + norms ----------------------------------
__global__ void split_cb_kernel(const float* __restrict__ cb,
                                __nv_bfloat16* __restrict__ out)
{
    size_t i = (size_t)blockIdx.x * blockDim.x + threadIdx.x;
    if (i >= (size_t)NCB * CBS * CDIM) return;
    out[i] = __float2bfloat16(cb[i]);
}

// norms + per-stage max||c||^2 (atomicMax on positive-float bits: order-free)
__global__ void norm_kernel(const float* __restrict__ cb, float* __restrict__ out,
                            unsigned* __restrict__ maxC2u, int rows)
{
    int w = (blockIdx.x * blockDim.x + threadIdx.x) >> 5;
    int lane = threadIdx.x & 31;
    if (w >= rows) return;
    const float* r = cb + (size_t)w * CDIM;
    float s = 0.f;
#pragma unroll
    for (int q = 0; q < 4; ++q) { float v = r[lane + q * 32]; s += v * v; }
#pragma unroll
    for (int off = 16; off >= 1; off >>= 1) s += __shfl_xor_sync(0xffffffffu, s, off);
    if (lane == 0) {
        out[w] = s;
        atomicMax(&maxC2u[w >> 10], __float_as_uint(s));
    }
}

// ---------------- phase 1: approx distances, single bf16 pass ---------------
// Per CTA: 128 tokens x 1024 codes; A = bf16(ze) resident; B = 64-code chunks
// double-buffered. d~ = ||c||^2 - 2*(a.a) written fp16; per-row running min of
// the SAME fp16-rounded values -> global atomicMin (order-free => exact dmin).
#define PSTR 272                        // smem row stride (256B data + 16 pad)
#define P1_B (128 * PSTR)               // 34816
#define P1_BBUF (64 * PSTR)             // 17408
#define P1_TOT (P1_B + 2 * P1_BBUF)     // 69632 dynamic smem

__global__ __launch_bounds__(256) void distApprox_kernel(
    const __nv_bfloat16* __restrict__ zeA,   // [BT_TOK][128]
    const __nv_bfloat16* __restrict__ cbA,   // stage base [CBS][128]
    const float* __restrict__ cbn,           // stage base [CBS]
    __half* __restrict__ D,                  // [BT_TOK][CBS]
    unsigned* __restrict__ dminU)            // per-token min bits
{
    extern __shared__ char smem[];
    const uint32_t sb = (uint32_t)__cvta_generic_to_shared(smem);
    const int tid = threadIdx.x;
    const int lane = tid & 31, wid = tid >> 5;
    const int rowband = wid & 3;
    const int colhalf = wid >> 2;
    const int gid = lane >> 2, tig = lane & 3;
    const int m0 = blockIdx.x * 128;

    {
        const __nv_bfloat16* src = zeA + (size_t)m0 * CDIM;
#pragma unroll
        for (int it = 0; it < 8; ++it) {
            int idx = tid + it * 256;
            int row = idx >> 4, piece = idx & 15;
            cp16(sb + row * PSTR + piece * 16, src + (size_t)row * CDIM + piece * 8);
        }
    }
    CP_COMMIT;
    {
#pragma unroll
        for (int it = 0; it < 4; ++it) {
            int idx = tid + it * 256;
            int row = idx >> 4, piece = idx & 15;
            cp16(sb + P1_B + row * PSTR + piece * 16,
                 cbA + (size_t)row * CDIM + piece * 8);
        }
    }
    CP_COMMIT;

    const uint32_t aBase = sb + (rowband * 32 + (lane & 15)) * PSTR + (lane >> 4) * 16;
    const uint32_t bLaneOff = (colhalf * 32 + (lane & 7)) * PSTR +
                              ((lane >> 3) & 1) * 16;

    float c[2][4][4];
#pragma unroll
    for (int rt = 0; rt < 2; ++rt)
#pragma unroll
        for (int ct = 0; ct < 4; ++ct)
#pragma unroll
            for (int v = 0; v < 4; ++v) c[rt][ct][v] = 0.f;

    float rmin[4] = {3.4e38f, 3.4e38f, 3.4e38f, 3.4e38f};

    for (int nc = 0; nc < 16; ++nc) {
        const int buf = nc & 1;
        if (nc + 1 < 16) {
            const __nv_bfloat16* src = cbA + (size_t)(nc + 1) * 64 * CDIM;
            const uint32_t dst = sb + P1_B + (buf ^ 1) * P1_BBUF;
#pragma unroll
            for (int it = 0; it < 4; ++it) {
                int idx = tid + it * 256;
                int row = idx >> 4, piece = idx & 15;
                cp16(dst + row * PSTR + piece * 16,
                     src + (size_t)row * CDIM + piece * 8);
            }
            CP_COMMIT;
            CP_WAIT1;
        } else {
            CP_WAIT0;
        }
        __syncthreads();

        const uint32_t bBase = sb + P1_B + buf * P1_BBUF + bLaneOff;
#pragma unroll
        for (int kc = 0; kc < 2; ++kc) {
#pragma unroll
            for (int ks = 0; ks < 4; ++ks) {
                const uint32_t off = kc * 128 + ks * 32;
                uint32_t a[2][4];
                LDMX4(a[0], aBase + off);
                LDMX4(a[1], aBase + 16 * PSTR + off);
                uint32_t b[4][2];
#pragma unroll
                for (int ct = 0; ct < 4; ++ct)
                    LDMX2(b[ct], bBase + ct * 8 * PSTR + off);
#pragma unroll
                for (int rt = 0; rt < 2; ++rt)
#pragma unroll
                    for (int ct = 0; ct < 4; ++ct)
                        MMA16816(c[rt][ct], a[rt], b[ct]);
            }
        }

        {
            const int colb = nc * 64 + colhalf * 32;
#pragma unroll
            for (int rt = 0; rt < 2; ++rt) {
                const int row = m0 + rowband * 32 + rt * 16 + gid;
                __half2* d0 = (__half2*)(D + (size_t)row * CBS);
                __half2* d1 = (__half2*)(D + (size_t)(row + 8) * CBS);
#pragma unroll
                for (int ct = 0; ct < 4; ++ct) {
                    const int col = colb + ct * 8 + tig * 2;
                    const float cn0 = cbn[col], cn1 = cbn[col + 1];
                    __half2 h0 = __floats2half2_rn(cn0 - 2.0f * c[rt][ct][0],
                                                   cn1 - 2.0f * c[rt][ct][1]);
                    __half2 h1 = __floats2half2_rn(cn0 - 2.0f * c[rt][ct][2],
                                                   cn1 - 2.0f * c[rt][ct][3]);
                    d0[col >> 1] = h0;
                    d1[col >> 1] = h1;
                    float2 f0 = __half22float2(h0);
                    float2 f1 = __half22float2(h1);
                    rmin[rt * 2]     = fminf(rmin[rt * 2],     fminf(f0.x, f0.y));
                    rmin[rt * 2 + 1] = fminf(rmin[rt * 2 + 1], fminf(f1.x, f1.y));
                    c[rt][ct][0] = 0.f; c[rt][ct][1] = 0.f;
                    c[rt][ct][2] = 0.f; c[rt][ct][3] = 0.f;
                }
            }
        }
        __syncthreads();
    }

#pragma unroll
    for (int rt = 0; rt < 2; ++rt) {
        const int row = m0 + rowband * 32 + rt * 16 + gid;
        atomicMin(&dminU[row],     fmap(rmin[rt * 2]));
        atomicMin(&dminU[row + 8], fmap(rmin[rt * 2 + 1]));
    }
}

// ---------------- phase 2: certified rescore + codes + loss + R update ------
// Per warp = 1 token (32768 warps — full parallelism). thr = dmin + margin
// (same values as R11/R13); rescore candidates with the exact fp32 chain
// (acc = fma(ze_k, cb_k, acc), k asc; d = cbn - 2*acc); key-min == full fp32
// argmin. Then codes + loss + R[t] -= G[idx] inline (identical arithmetic).
__global__ __launch_bounds__(256) void argminFused_kernel(
    const float* __restrict__ Ze, const __half* __restrict__ D,
    const float* __restrict__ cb, const float* __restrict__ cbn,
    const unsigned* __restrict__ maxC2u, int stage,
    const unsigned* __restrict__ dminU,
    const float* __restrict__ G, float* __restrict__ R,
    float* __restrict__ out_codes, float* __restrict__ partial)
{
    __shared__ float zrow[8][128];
    const int lane = threadIdx.x & 31, wid = threadIdx.x >> 5;
    const int t = blockIdx.x * 8 + wid;

    const float* zep = Ze + (size_t)t * CDIM;
    float zn2 = 0.f;
#pragma unroll
    for (int q = 0; q < 4; ++q) {
        float v = zep[lane + q * 32];
        zrow[wid][lane + q * 32] = v;
        zn2 += v * v;
    }
#pragma unroll
    for (int off = 16; off >= 1; off >>= 1)
        zn2 += __shfl_xor_sync(0xffffffffu, zn2, off);
    __syncwarp();

    const float maxC2 = __uint_as_float(maxC2u[stage]);
    const float zn = sqrtf(zn2), maxC = sqrtf(maxC2);
    const float margin = ldexpf(zn * maxC, -6) +
                         ldexpf(maxC2 + 2.0f * zn * maxC, -9);
    const float thr = funmap(dminU[t]) + margin;

    const __half2* drow = (const __half2*)(D + (size_t)t * CBS);
    unsigned long long best = ~0ull;
    for (int i = 0; i < 16; ++i) {
        float2 v = __half22float2(drow[i * 32 + lane]);
        const int nbase = (i * 32 + lane) * 2;
#pragma unroll
        for (int h = 0; h < 2; ++h) {
            float dv = (h == 0) ? v.x : v.y;
            if (dv <= thr) {
                const int n = nbase + h;
                const float* cr = cb + (size_t)n * CDIM;
                float acc = 0.f;
#pragma unroll 16
                for (int k = 0; k < 128; ++k)
                    acc = fmaf(zrow[wid][k], cr[k], acc);
                float dd = cbn[n] - 2.0f * acc;
                unsigned long long key =
                    ((unsigned long long)fmap(dd) << 32) | (unsigned)n;
                if (key < best) best = key;
            }
        }
    }
#pragma unroll
    for (int off = 16; off >= 1; off >>= 1) {
        unsigned long long o = __shfl_xor_sync(0xffffffffu, best, off);
        if (o < best) best = o;
    }
    const unsigned idx = (unsigned)(best & 0xffffffffu);

    // loss: sum over CDIM of (ze - zq)^2
    const float* cq = cb + (size_t)idx * CDIM;
    float s = 0.f;
#pragma unroll
    for (int q = 0; q < 4; ++q) {
        float d = zrow[wid][lane + q * 32] - cq[lane + q * 32];
        s += d * d;
    }
#pragma unroll
    for (int off = 16; off >= 1; off >>= 1)
        s += __shfl_xor_sync(0xffffffffu, s, off);
    if (lane == 0) {
        partial[t] = s;
        out_codes[(size_t)t * NCB + stage] = (float)idx;
    }

    // R[t] -= G[idx]  (512 floats = 4 float4 per lane; identical arithmetic)
    float4* R4 = (float4*)(R + (size_t)t * ENC);
    const float4* G4 = (const float4*)(G + (size_t)idx * ENC);
#pragma unroll
    for (int q = 0; q < 4; ++q) {
        int o = lane + q * 32;
        float4 r = R4[o], g = G4[o];
        r.x -= g.x; r.y -= g.y; r.z -= g.z; r.w -= g.w;
        R4[o] = r;
    }
}

__global__ void final_loss_kernel(const float* __restrict__ partial, float* __restrict__ out)
{
    __shared__ float s[256];
    float v = 0.f;
    const int per = (NCB * BT_TOK) / 256;   // 1024
    for (int q = 0; q < per; ++q) v += partial[threadIdx.x * per + q];
    s[threadIdx.x] = v;
    __syncthreads();
    for (int st = 128; st > 0; st >>= 1) {
        if (threadIdx.x < st) s[threadIdx.x] += s[threadIdx.x + st];
        __syncthreads();
    }
    if (threadIdx.x == 0)
        out[(size_t)BT_TOK * NCB] = 1.25f * s[0] / (float)((size_t)BT_TOK * CDIM);
}

// ---------------- launch ----------------------------------------------------
extern "C" void kernel_launch(void* const* d_in, const int* in_sizes, int n_in,
                              void* d_out, int out_size)
{
    const float* z    = (const float*)d_in[0];   // (16,2048,768)
    const float* Win  = (const float*)d_in[1];   // (768,512)
    const float* bin  = (const float*)d_in[2];   // (512,)
    const float* cbs  = (const float*)d_in[3];   // (8,1024,128)
    const float* inw  = (const float*)d_in[4];   // (8,512,128)
    const float* outw = (const float*)d_in[5];   // (8,128,512)
    float* out = (float*)d_out;

    float *gR, *gZe, *gCbn, *gLP, *gG;
    __half* gD;
    __nv_bfloat16 *gZeA, *gCbA;
    unsigned *gMx, *gDm;
    cudaGetSymbolAddress((void**)&gR,   g_R);
    cudaGetSymbolAddress((void**)&gZe,  g_Ze);
    cudaGetSymbolAddress((void**)&gZeA, g_zeA);
    cudaGetSymbolAddress((void**)&gCbA, g_cbA);
    cudaGetSymbolAddress((void**)&gCbn, g_cbnorm);
    cudaGetSymbolAddress((void**)&gMx,  g_maxC2u);
    cudaGetSymbolAddress((void**)&gLP,  g_lossPartial);
    cudaGetSymbolAddress((void**)&gG,   g_G);
    cudaGetSymbolAddress((void**)&gD,   g_D);
    cudaGetSymbolAddress((void**)&gDm,  g_dminU);

    cudaFuncSetAttribute(distApprox_kernel,
                         cudaFuncAttributeMaxDynamicSharedMemorySize, P1_TOT);

    // 1. residual = z @ W_in + b_in
    sgemm4<true, false><<<dim3(BT_TOK / 128, ENC / 128, 1), 256>>>(
        z, Win, gR, bin, nullptr, nullptr, IN_DIM, ENC, 0, 0, 0);

    // 2. codebook norms (+ per-stage max) + bf16 a-planes
    norm_kernel<<<(NCB * CBS * 32) / 256, 256>>>(cbs, gCbn, gMx, NCB * CBS);
    split_cb_kernel<<<(NCB * CBS * CDIM) / 256, 256>>>(cbs, gCbA);

    // 3. dec tables: G_i = cb_i @ out_w_i (batched over blockIdx.z)
    sgemm4<false, false><<<dim3(CBS / 128, ENC / 128, NCB), 256>>>(
        cbs, outw, gG, nullptr, nullptr, nullptr, CDIM, ENC,
        (size_t)CBS * CDIM, (size_t)CDIM * ENC, (size_t)CBS * ENC);

    for (int i = 0; i < NCB; ++i) {
        const float* cb_i = cbs + (size_t)i * CBS * CDIM;

        // z_e = R @ in_w[i]  (fp32 + bf16 a-plane; resets dminU)
        sgemm4<false, true><<<dim3(BT_TOK / 128, 1, 1), 256>>>(
            gR, inw + (size_t)i * ENC * CDIM, gZe, nullptr, gZeA, gDm,
            ENC, CDIM, 0, 0, 0);

        // phase 1: approx distances + per-token dmin
        distApprox_kernel<<<BT_TOK / 128, 256, P1_TOT>>>(
            gZeA, gCbA + (size_t)i * CBS * CDIM, gCbn + (size_t)i * CBS, gD, gDm);

        // phase 2: certified exact argmin + codes + loss + R -= G[idx]
        argminFused_kernel<<<BT_TOK / 8, 256>>>(
            gZe, gD, cb_i, gCbn + (size_t)i * CBS, gMx, i, gDm,
            gG + (size_t)i * CBS * ENC, gR, out, gLP + (size_t)i * BT_TOK);
    }

    final_loss_kernel<<<1, 256>>>(gLP, out);
}